// round 1
// baseline (speedup 1.0000x reference)
#include <cuda_runtime.h>

#define BB 8
#define VPB 4096
#define VV 32768
#define EE 196608
#define NF 128
#define IN0 259
#define LDF 260

// ---------------- static scratch (no allocations allowed) ----------------
__device__ float g_P1[BB*56*56*128];
__device__ float g_P2[BB*28*28*128];
__device__ float g_P3[BB*14*14*128];
__device__ float g_P4[BB*7*7*128];
__device__ float g_feat[(long)VV*LDF];
__device__ float g_h[(long)VV*NF];
__device__ float g_t[(long)VV*NF];
__device__ float g_Ae[(long)VV*NF];
__device__ float g_agg[(long)VV*NF];
__device__ float g_A3[VV*3];
__device__ float g_agg3[VV*3];

// ---------------- generic tiled fp32 GEMM, N = 128 fixed ----------------
// MODE 0: C = A@W
// MODE 1: C = relu(A@W + D)
// MODE 2: C = S + relu(A@W + D)
// KMAJOR: A stored K-major (A[k*lda + m]) — used for fmap^T @ w_lin projection
template<int MODE, bool KMAJOR>
__global__ void gemm_kernel(const float* __restrict__ A, int lda, long strideA,
                            const float* __restrict__ W,
                            const float* __restrict__ Dp,
                            const float* __restrict__ Sp,
                            float* __restrict__ C, long strideC,
                            int M, int K)
{
    __shared__ float As[32][65];
    __shared__ float Ws[32][128];
    A += blockIdx.z * strideA;
    C += blockIdx.z * strideC;
    int tid = threadIdx.x;
    int m0 = blockIdx.x * 64;
    float acc[8][4];
#pragma unroll
    for (int i = 0; i < 8; i++)
#pragma unroll
        for (int j = 0; j < 4; j++) acc[i][j] = 0.f;
    int ty = tid >> 5, tx = tid & 31;

    for (int k0 = 0; k0 < K; k0 += 32) {
        if (KMAJOR) {
            int lm = tid & 63;
            int lk0 = tid >> 6;
#pragma unroll
            for (int i = 0; i < 8; i++) {
                int lk = lk0 + i * 4;
                int gm = m0 + lm, gk = k0 + lk;
                float val = 0.f;
                if (gm < M) val = A[(long)gk * lda + gm];
                As[lk][lm] = val;
            }
        } else {
            int lk = tid & 31;
            int lr0 = tid >> 5;
#pragma unroll
            for (int i = 0; i < 8; i++) {
                int lr = lr0 + i * 8;
                int gm = m0 + lr, gk = k0 + lk;
                float val = 0.f;
                if (gm < M && gk < K) val = A[(long)gm * lda + gk];
                As[lk][lr] = val;
            }
        }
#pragma unroll
        for (int i = 0; i < 16; i++) {
            int idx = i * 256 + tid;
            int wk = idx >> 7, wn = idx & 127;
            int gk = k0 + wk;
            Ws[wk][wn] = (gk < K) ? W[(long)gk * 128 + wn] : 0.f;
        }
        __syncthreads();
#pragma unroll
        for (int kk = 0; kk < 32; kk++) {
            float a[8];
#pragma unroll
            for (int i = 0; i < 8; i++) a[i] = As[kk][ty * 8 + i];
            float4 w = *(const float4*)&Ws[kk][tx * 4];
#pragma unroll
            for (int i = 0; i < 8; i++) {
                acc[i][0] += a[i] * w.x;
                acc[i][1] += a[i] * w.y;
                acc[i][2] += a[i] * w.z;
                acc[i][3] += a[i] * w.w;
            }
        }
        __syncthreads();
    }

#pragma unroll
    for (int i = 0; i < 8; i++) {
        int gm = m0 + ty * 8 + i;
        if (gm >= M) continue;
        int gn = tx * 4;
        long off = (long)gm * 128 + gn;
        float4 v = make_float4(acc[i][0], acc[i][1], acc[i][2], acc[i][3]);
        if (MODE >= 1) {
            float4 d = *(const float4*)&Dp[off];
            v.x = fmaxf(v.x + d.x, 0.f);
            v.y = fmaxf(v.y + d.y, 0.f);
            v.z = fmaxf(v.z + d.z, 0.f);
            v.w = fmaxf(v.w + d.w, 0.f);
        }
        if (MODE == 2) {
            float4 s = *(const float4*)&Sp[off];
            v.x += s.x; v.y += s.y; v.z += s.z; v.w += s.w;
        }
        *(float4*)&C[off] = v;
    }
}

// ---------------- vert-align gather + feat assembly ----------------
__device__ __forceinline__ float gatherP(const float* __restrict__ P, int s, float scale,
                                         int b, float ww, float hh, int t)
{
    float x = ww * scale;  // scale = s/224 (exact power of two) == w / (224/s)
    float y = hh * scale;
    float x1 = floorf(x), y1 = floorf(y);
    float x2 = fminf(ceilf(x), (float)(s - 1));
    float y2 = fminf(ceilf(y), (float)(s - 1));
    float wgt = (x2 - x1) * (y2 - y1);   // w12,w21,w22 are identically zero in the reference
    if (wgt == 0.f) return 0.f;
    int pix = (b * s + (int)x1) * s + (int)y1;
    return wgt * P[(long)pix * 128 + t];
}

__global__ void build_feat(const float* __restrict__ vpos, const float* __restrict__ vfeat,
                           float* __restrict__ feat)
{
    int t = threadIdx.x;
#pragma unroll
    for (int q = 0; q < 4; q++) {
        int v = blockIdx.x * 4 + q;
        int b = v >> 12;
        float px = vpos[v * 3 + 0];
        float py = vpos[v * 3 + 1];
        float pz = vpos[v * 3 + 2];
        float hh = fminf(fmaxf(248.f * (py / pz) + 111.5f, 0.f), 223.f);
        float ww = fminf(fmaxf(248.f * (px / (-pz)) + 111.5f, 0.f), 223.f);
        float al = 0.f;
        al += gatherP(g_P1, 56, 0.25f,    b, ww, hh, t);
        al += gatherP(g_P2, 28, 0.125f,   b, ww, hh, t);
        al += gatherP(g_P3, 14, 0.0625f,  b, ww, hh, t);
        al += gatherP(g_P4, 7,  0.03125f, b, ww, hh, t);
        long base = (long)v * LDF;
        feat[base + t] = vfeat[(long)v * 128 + t];
        if (t < 3) feat[base + 128 + t] = vpos[v * 3 + t];
        feat[base + 131 + t] = al;
    }
}

// ---------------- edge scatter (segment_sum) ----------------
__global__ void scatter_add(const float* __restrict__ Asrc, const int* __restrict__ ei,
                            float* __restrict__ agg)
{
    int e = blockIdx.x * 4 + (threadIdx.x >> 7);
    int t = threadIdx.x & 127;
    int s = ei[e];
    int d = ei[EE + e];
    atomicAdd(&agg[(long)d * 128 + t], Asrc[(long)s * 128 + t]);
}

// ---------------- final head: N=3 gconv + tanh refine ----------------
__global__ void gemv3(const float* __restrict__ X, const float* __restrict__ Wt,
                      float* __restrict__ Y)
{
    int warp = (blockIdx.x * blockDim.x + threadIdx.x) >> 5;
    int lane = threadIdx.x & 31;
    if (warp >= VV) return;
    float a0 = 0.f, a1 = 0.f, a2 = 0.f;
#pragma unroll
    for (int k = lane; k < 128; k += 32) {
        float xv = X[(long)warp * 128 + k];
        a0 += xv * Wt[k * 3 + 0];
        a1 += xv * Wt[k * 3 + 1];
        a2 += xv * Wt[k * 3 + 2];
    }
#pragma unroll
    for (int off = 16; off; off >>= 1) {
        a0 += __shfl_down_sync(0xffffffffu, a0, off);
        a1 += __shfl_down_sync(0xffffffffu, a1, off);
        a2 += __shfl_down_sync(0xffffffffu, a2, off);
    }
    if (lane == 0) {
        Y[warp * 3 + 0] = a0;
        Y[warp * 3 + 1] = a1;
        Y[warp * 3 + 2] = a2;
    }
}

__global__ void scatter3(const float* __restrict__ A3, const int* __restrict__ ei,
                         float* __restrict__ agg3)
{
    int e = blockIdx.x * 256 + threadIdx.x;
    if (e >= EE) return;
    int s = ei[e], d = ei[EE + e];
    atomicAdd(&agg3[d * 3 + 0], A3[s * 3 + 0]);
    atomicAdd(&agg3[d * 3 + 1], A3[s * 3 + 1]);
    atomicAdd(&agg3[d * 3 + 2], A3[s * 3 + 2]);
}

__global__ void final_pos(const float* __restrict__ X, const float* __restrict__ Wt,
                          const float* __restrict__ agg3, const float* __restrict__ vpos,
                          float* __restrict__ outpos)
{
    int warp = (blockIdx.x * blockDim.x + threadIdx.x) >> 5;
    int lane = threadIdx.x & 31;
    if (warp >= VV) return;
    float a0 = 0.f, a1 = 0.f, a2 = 0.f;
#pragma unroll
    for (int k = lane; k < 128; k += 32) {
        float xv = X[(long)warp * 128 + k];
        a0 += xv * Wt[k * 3 + 0];
        a1 += xv * Wt[k * 3 + 1];
        a2 += xv * Wt[k * 3 + 2];
    }
#pragma unroll
    for (int off = 16; off; off >>= 1) {
        a0 += __shfl_down_sync(0xffffffffu, a0, off);
        a1 += __shfl_down_sync(0xffffffffu, a1, off);
        a2 += __shfl_down_sync(0xffffffffu, a2, off);
    }
    if (lane == 0) {
        float r0 = fmaxf(a0 + agg3[warp * 3 + 0], 0.f);
        float r1 = fmaxf(a1 + agg3[warp * 3 + 1], 0.f);
        float r2 = fmaxf(a2 + agg3[warp * 3 + 2], 0.f);
        outpos[warp * 3 + 0] = vpos[warp * 3 + 0] + tanhf(r0);
        outpos[warp * 3 + 1] = vpos[warp * 3 + 1] + tanhf(r1);
        outpos[warp * 3 + 2] = vpos[warp * 3 + 2] + tanhf(r2);
    }
}

// ---------------- launch ----------------
extern "C" void kernel_launch(void* const* d_in, const int* in_sizes, int n_in,
                              void* d_out, int out_size)
{
    const float* f1   = (const float*)d_in[0];
    const float* f2   = (const float*)d_in[1];
    const float* f3   = (const float*)d_in[2];
    const float* f4   = (const float*)d_in[3];
    const float* vpos = (const float*)d_in[4];
    const float* vfea = (const float*)d_in[5];
    const int*   ei   = (const int*)d_in[6];
    const float* wlin = (const float*)d_in[7];
    const float* r0p  = (const float*)d_in[8];
    const float* r0a0 = (const float*)d_in[9];
    const float* r0a1 = (const float*)d_in[10];
    const float* r0b0 = (const float*)d_in[11];
    const float* r0b1 = (const float*)d_in[12];
    const float* r1a0 = (const float*)d_in[13];
    const float* r1a1 = (const float*)d_in[14];
    const float* r1b0 = (const float*)d_in[15];
    const float* r1b1 = (const float*)d_in[16];
    const float* r2a0 = (const float*)d_in[17];
    const float* r2a1 = (const float*)d_in[18];
    const float* r2b0 = (const float*)d_in[19];
    const float* r2b1 = (const float*)d_in[20];
    const float* gw0  = (const float*)d_in[21];
    const float* gw1  = (const float*)d_in[22];

    float* out  = (float*)d_out;
    float* hout = out + (long)VV * 3;

    float *P1, *P2, *P3, *P4, *feat, *hb, *tb, *Ab, *agg, *A3, *agg3;
    cudaGetSymbolAddress((void**)&P1,   g_P1);
    cudaGetSymbolAddress((void**)&P2,   g_P2);
    cudaGetSymbolAddress((void**)&P3,   g_P3);
    cudaGetSymbolAddress((void**)&P4,   g_P4);
    cudaGetSymbolAddress((void**)&feat, g_feat);
    cudaGetSymbolAddress((void**)&hb,   g_h);
    cudaGetSymbolAddress((void**)&tb,   g_t);
    cudaGetSymbolAddress((void**)&Ab,   g_Ae);
    cudaGetSymbolAddress((void**)&agg,  g_agg);
    cudaGetSymbolAddress((void**)&A3,   g_A3);
    cudaGetSymbolAddress((void**)&agg3, g_agg3);

    const size_t VN4 = (size_t)VV * NF * sizeof(float);

    // 1) per-pixel feature projections: P_m = fmap_m^T @ w_lin_slice
    gemm_kernel<0, true><<<dim3((3136 + 63) / 64, 1, BB), 256>>>(
        f1, 3136, (long)256 * 3136, wlin + (long)0 * 128, nullptr, nullptr,
        P1, (long)3136 * 128, 3136, 256);
    gemm_kernel<0, true><<<dim3((784 + 63) / 64, 1, BB), 256>>>(
        f2, 784, (long)512 * 784, wlin + (long)256 * 128, nullptr, nullptr,
        P2, (long)784 * 128, 784, 512);
    gemm_kernel<0, true><<<dim3((196 + 63) / 64, 1, BB), 256>>>(
        f3, 196, (long)1024 * 196, wlin + (long)768 * 128, nullptr, nullptr,
        P3, (long)196 * 128, 196, 1024);
    gemm_kernel<0, true><<<dim3((49 + 63) / 64, 1, BB), 256>>>(
        f4, 49, (long)2048 * 49, wlin + (long)1792 * 128, nullptr, nullptr,
        P4, (long)49 * 128, 49, 2048);

    // 2) assemble feat = [vertex_features | pos | vert_align @ w_lin]
    build_feat<<<VV / 4, 128>>>(vpos, vfea, feat);

    dim3 gV(512, 1, 1);
#define GEMM0(Ap, ldap, Wp, Kp, Cp) \
    gemm_kernel<0, false><<<gV, 256>>>(Ap, ldap, 0, Wp, nullptr, nullptr, Cp, 0, VV, Kp)
#define GEMM1(Ap, ldap, Wp, Kp, Dp, Cp) \
    gemm_kernel<1, false><<<gV, 256>>>(Ap, ldap, 0, Wp, Dp, nullptr, Cp, 0, VV, Kp)
#define GEMM2(Ap, ldap, Wp, Kp, Dp, Sp, Cp) \
    gemm_kernel<2, false><<<gV, 256>>>(Ap, ldap, 0, Wp, Dp, Sp, Cp, 0, VV, Kp)
#define SCATTER(Ap) \
    cudaMemsetAsync(agg, 0, VN4); \
    scatter_add<<<EE / 4, 512>>>(Ap, ei, agg)

    // ---- resg block 0 (input feat, K=259, projected skip) ----
    GEMM0(feat, LDF, r0p, IN0, hb);           // skip = feat @ r0p
    GEMM0(feat, LDF, r0a1, IN0, Ab);
    SCATTER(Ab);
    GEMM1(feat, LDF, r0a0, IN0, agg, tb);     // g1 = relu(feat@a0 + agg)
    GEMM0(tb, 128, r0b1, 128, Ab);
    SCATTER(Ab);
    GEMM2(tb, 128, r0b0, 128, agg, hb, hb);   // h0 = skip + relu(g1@b0 + agg)

    // ---- resg block 1 ----
    GEMM0(hb, 128, r1a1, 128, Ab);
    SCATTER(Ab);
    GEMM1(hb, 128, r1a0, 128, agg, tb);
    GEMM0(tb, 128, r1b1, 128, Ab);
    SCATTER(Ab);
    GEMM2(tb, 128, r1b0, 128, agg, hb, hb);

    // ---- resg block 2 (final h written straight into d_out) ----
    GEMM0(hb, 128, r2a1, 128, Ab);
    SCATTER(Ab);
    GEMM1(hb, 128, r2a0, 128, agg, tb);
    GEMM0(tb, 128, r2b1, 128, Ab);
    SCATTER(Ab);
    GEMM2(tb, 128, r2b0, 128, agg, hb, hout);

    // ---- position head: pos + tanh(gconv(h, gw0, gw1)) ----
    gemv3<<<VV / 8, 256>>>(hout, gw1, A3);
    cudaMemsetAsync(agg3, 0, (size_t)VV * 3 * sizeof(float));
    scatter3<<<(EE + 255) / 256, 256>>>(A3, ei, agg3);
    final_pos<<<VV / 8, 256>>>(hout, gw0, agg3, vpos, out);

#undef GEMM0
#undef GEMM1
#undef GEMM2
#undef SCATTER
}

// round 2
// speedup vs baseline: 1.4600x; 1.4600x over previous
#include <cuda_runtime.h>

#define BB 8
#define VV 32768
#define EE 196608
#define NF 128
#define IN0 259
#define LDF 260

// ---------------- static scratch (no allocations allowed) ----------------
__device__ float g_P1[BB*56*56*128];
__device__ float g_P2[BB*28*28*128];
__device__ float g_P3[BB*14*14*128];
__device__ float g_P4[BB*7*7*128];
__device__ float g_feat[(long)VV*LDF];
__device__ float g_h[(long)VV*NF];
__device__ float g_t[(long)VV*NF];
__device__ float g_Ae[(long)VV*NF];
__device__ float g_agg[(long)VV*NF];
__device__ float g_A3[VV*3];
__device__ float g_agg3[VV*3];
// CSR scratch
__device__ int g_deg[VV];
__device__ int g_off[VV];
__device__ int g_cur[VV];
__device__ int g_bsum[256];
__device__ int g_eid[EE];

// ---------------- 128x128 tiled fp32 GEMM, N = 128 fixed ----------------
// MODE 0: C = A@W          MODE 1: C = relu(A@W + D)    MODE 2: C = S + relu(A@W + D)
// KMAJOR: A stored K-major (A[k*lda + m])
// ATOMIC: accumulate C += partial (split-K; C pre-zeroed); forces MODE 0 path
template<int MODE, bool KMAJOR, bool ATOMIC>
__global__ __launch_bounds__(256, 2)
void gemm128(const float* __restrict__ A, int lda, long strideA,
             const float* __restrict__ W,
             const float* __restrict__ Dp, const float* __restrict__ Sp,
             float* __restrict__ C, long strideC,
             int M, int K)
{
    __shared__ float As[16][132];
    __shared__ float Ws[16][128];
    A += blockIdx.z * strideA;
    C += blockIdx.z * strideC;
    int tid = threadIdx.x;
    int m0 = blockIdx.x * 128;
    int chunk = K / gridDim.y;
    int kbeg = chunk * blockIdx.y;
    int kend = (blockIdx.y == gridDim.y - 1) ? K : kbeg + chunk;

    float acc[8][8];
#pragma unroll
    for (int i = 0; i < 8; i++)
#pragma unroll
        for (int j = 0; j < 8; j++) acc[i][j] = 0.f;

    int tx = tid & 15, ty = tid >> 4;

    for (int k0 = kbeg; k0 < kend; k0 += 16) {
        if (KMAJOR) {
#pragma unroll
            for (int i = 0; i < 2; i++) {
                int q = i * 256 + tid;          // 512 float4 slots
                int k = q >> 5, m4 = (q & 31) * 4;
                int gk = k0 + k;
#pragma unroll
                for (int j = 0; j < 4; j++) {
                    int gm = m0 + m4 + j;
                    float val = 0.f;
                    if (gk < kend && gm < M) val = A[(long)gk * lda + gm];
                    As[k][m4 + j] = val;
                }
            }
        } else {
#pragma unroll
            for (int i = 0; i < 2; i++) {
                int q = i * 256 + tid;
                int row = q >> 2, kq = (q & 3) * 4;
                int gm = m0 + row, gk = k0 + kq;
                float4 v;
                if (gm < M && gk + 3 < kend) {
                    v = *(const float4*)&A[(long)gm * lda + gk];
                } else {
                    v.x = (gm < M && gk + 0 < kend) ? A[(long)gm * lda + gk + 0] : 0.f;
                    v.y = (gm < M && gk + 1 < kend) ? A[(long)gm * lda + gk + 1] : 0.f;
                    v.z = (gm < M && gk + 2 < kend) ? A[(long)gm * lda + gk + 2] : 0.f;
                    v.w = (gm < M && gk + 3 < kend) ? A[(long)gm * lda + gk + 3] : 0.f;
                }
                As[kq + 0][row] = v.x;
                As[kq + 1][row] = v.y;
                As[kq + 2][row] = v.z;
                As[kq + 3][row] = v.w;
            }
        }
#pragma unroll
        for (int i = 0; i < 2; i++) {
            int q = i * 256 + tid;
            int wk = q >> 5, wn = (q & 31) * 4;
            int gk = k0 + wk;
            float4 v = make_float4(0.f, 0.f, 0.f, 0.f);
            if (gk < kend) v = *(const float4*)&W[(long)gk * 128 + wn];
            *(float4*)&Ws[wk][wn] = v;
        }
        __syncthreads();
#pragma unroll
        for (int kk = 0; kk < 16; kk++) {
            float4 a0 = *(const float4*)&As[kk][ty * 8];
            float4 a1 = *(const float4*)&As[kk][ty * 8 + 4];
            float4 b0 = *(const float4*)&Ws[kk][tx * 8];
            float4 b1 = *(const float4*)&Ws[kk][tx * 8 + 4];
            float a[8] = {a0.x, a0.y, a0.z, a0.w, a1.x, a1.y, a1.z, a1.w};
            float b[8] = {b0.x, b0.y, b0.z, b0.w, b1.x, b1.y, b1.z, b1.w};
#pragma unroll
            for (int i = 0; i < 8; i++)
#pragma unroll
                for (int j = 0; j < 8; j++) acc[i][j] += a[i] * b[j];
        }
        __syncthreads();
    }

#pragma unroll
    for (int i = 0; i < 8; i++) {
        int gm = m0 + ty * 8 + i;
        if (gm >= M) continue;
#pragma unroll
        for (int j = 0; j < 8; j += 4) {
            int gn = tx * 8 + j;
            long off = (long)gm * 128 + gn;
            float4 v = make_float4(acc[i][j], acc[i][j + 1], acc[i][j + 2], acc[i][j + 3]);
            if (ATOMIC) {
                atomicAdd(&C[off + 0], v.x);
                atomicAdd(&C[off + 1], v.y);
                atomicAdd(&C[off + 2], v.z);
                atomicAdd(&C[off + 3], v.w);
            } else {
                if (MODE >= 1) {
                    float4 d = *(const float4*)&Dp[off];
                    v.x = fmaxf(v.x + d.x, 0.f);
                    v.y = fmaxf(v.y + d.y, 0.f);
                    v.z = fmaxf(v.z + d.z, 0.f);
                    v.w = fmaxf(v.w + d.w, 0.f);
                }
                if (MODE == 2) {
                    float4 s = *(const float4*)&Sp[off];
                    v.x += s.x; v.y += s.y; v.z += s.z; v.w += s.w;
                }
                *(float4*)&C[off] = v;
            }
        }
    }
}

// ---------------- vert-align gather + feat assembly ----------------
__device__ __forceinline__ float gatherP(const float* __restrict__ P, int s, float scale,
                                         int b, float ww, float hh, int t)
{
    float x = ww * scale;
    float y = hh * scale;
    float x1 = floorf(x), y1 = floorf(y);
    float x2 = fminf(ceilf(x), (float)(s - 1));
    float y2 = fminf(ceilf(y), (float)(s - 1));
    float wgt = (x2 - x1) * (y2 - y1);   // w12,w21,w22 are identically zero in the reference
    if (wgt == 0.f) return 0.f;
    int pix = (b * s + (int)x1) * s + (int)y1;
    return wgt * P[(long)pix * 128 + t];
}

__global__ void build_feat(const float* __restrict__ vpos, const float* __restrict__ vfeat,
                           float* __restrict__ feat)
{
    int t = threadIdx.x;
#pragma unroll
    for (int q = 0; q < 4; q++) {
        int v = blockIdx.x * 4 + q;
        int b = v >> 12;
        float px = vpos[v * 3 + 0];
        float py = vpos[v * 3 + 1];
        float pz = vpos[v * 3 + 2];
        float hh = fminf(fmaxf(248.f * (py / pz) + 111.5f, 0.f), 223.f);
        float ww = fminf(fmaxf(248.f * (px / (-pz)) + 111.5f, 0.f), 223.f);
        float al = 0.f;
        al += gatherP(g_P1, 56, 0.25f,    b, ww, hh, t);
        al += gatherP(g_P2, 28, 0.125f,   b, ww, hh, t);
        al += gatherP(g_P3, 14, 0.0625f,  b, ww, hh, t);
        al += gatherP(g_P4, 7,  0.03125f, b, ww, hh, t);
        long base = (long)v * LDF;
        feat[base + t] = vfeat[(long)v * 128 + t];
        if (t < 3) feat[base + 128 + t] = vpos[v * 3 + t];
        feat[base + 131 + t] = al;
    }
}

// ---------------- CSR build (per-call, deterministic up to fp tolerance) ----
__global__ void k_hist(const int* __restrict__ ei) {
    int e = blockIdx.x * 256 + threadIdx.x;
    if (e < EE) atomicAdd(&g_deg[ei[EE + e]], 1);
}

__global__ void k_scan1() {   // 256 blocks x 128 thr: per-block exclusive scan
    __shared__ int sh[128];
    int v = blockIdx.x * 128 + threadIdx.x;
    int x = g_deg[v];
    sh[threadIdx.x] = x;
    __syncthreads();
    for (int d = 1; d < 128; d <<= 1) {
        int t = (threadIdx.x >= d) ? sh[threadIdx.x - d] : 0;
        __syncthreads();
        sh[threadIdx.x] += t;
        __syncthreads();
    }
    g_off[v] = sh[threadIdx.x] - x;
    if (threadIdx.x == 127) g_bsum[blockIdx.x] = sh[127];
}

__global__ void k_scan2() {   // 1 block x 256: exclusive scan of block sums
    __shared__ int sh[256];
    int t = threadIdx.x;
    int x = g_bsum[t];
    sh[t] = x;
    __syncthreads();
    for (int d = 1; d < 256; d <<= 1) {
        int v = (t >= d) ? sh[t - d] : 0;
        __syncthreads();
        sh[t] += v;
        __syncthreads();
    }
    g_bsum[t] = sh[t] - x;
}

__global__ void k_scan3() {
    int v = blockIdx.x * 128 + threadIdx.x;
    int o = g_off[v] + g_bsum[blockIdx.x];
    g_off[v] = o;
    g_cur[v] = o;
}

__global__ void k_fill(const int* __restrict__ ei) {
    int e = blockIdx.x * 256 + threadIdx.x;
    if (e >= EE) return;
    int p = atomicAdd(&g_cur[ei[EE + e]], 1);
    g_eid[p] = ei[e];
}

// ---------------- aggregation: gather-sum over CSR ----------------
__global__ void agg_gather(const float* __restrict__ Asrc, float* __restrict__ agg) {
    int v = blockIdx.x;
    int t = threadIdx.x;
    int s = g_off[v];
    int e = (v == VV - 1) ? EE : g_off[v + 1];
    float acc = 0.f;
    for (int j = s; j < e; j++)
        acc += Asrc[(long)g_eid[j] * 128 + t];
    agg[(long)v * 128 + t] = acc;
}

// ---------------- final head ----------------
__global__ void gemv3(const float* __restrict__ X, const float* __restrict__ Wt,
                      float* __restrict__ Y)
{
    int warp = (blockIdx.x * blockDim.x + threadIdx.x) >> 5;
    int lane = threadIdx.x & 31;
    if (warp >= VV) return;
    float a0 = 0.f, a1 = 0.f, a2 = 0.f;
#pragma unroll
    for (int k = lane; k < 128; k += 32) {
        float xv = X[(long)warp * 128 + k];
        a0 += xv * Wt[k * 3 + 0];
        a1 += xv * Wt[k * 3 + 1];
        a2 += xv * Wt[k * 3 + 2];
    }
#pragma unroll
    for (int off = 16; off; off >>= 1) {
        a0 += __shfl_down_sync(0xffffffffu, a0, off);
        a1 += __shfl_down_sync(0xffffffffu, a1, off);
        a2 += __shfl_down_sync(0xffffffffu, a2, off);
    }
    if (lane == 0) {
        Y[warp * 3 + 0] = a0;
        Y[warp * 3 + 1] = a1;
        Y[warp * 3 + 2] = a2;
    }
}

__global__ void k_agg3(const float* __restrict__ A3, float* __restrict__ agg3) {
    int v = blockIdx.x * 256 + threadIdx.x;
    if (v >= VV) return;
    int s = g_off[v];
    int e = (v == VV - 1) ? EE : g_off[v + 1];
    float a0 = 0.f, a1 = 0.f, a2 = 0.f;
    for (int j = s; j < e; j++) {
        int u = g_eid[j];
        a0 += A3[u * 3 + 0];
        a1 += A3[u * 3 + 1];
        a2 += A3[u * 3 + 2];
    }
    agg3[v * 3 + 0] = a0;
    agg3[v * 3 + 1] = a1;
    agg3[v * 3 + 2] = a2;
}

__global__ void final_pos(const float* __restrict__ X, const float* __restrict__ Wt,
                          const float* __restrict__ agg3, const float* __restrict__ vpos,
                          float* __restrict__ outpos)
{
    int warp = (blockIdx.x * blockDim.x + threadIdx.x) >> 5;
    int lane = threadIdx.x & 31;
    if (warp >= VV) return;
    float a0 = 0.f, a1 = 0.f, a2 = 0.f;
#pragma unroll
    for (int k = lane; k < 128; k += 32) {
        float xv = X[(long)warp * 128 + k];
        a0 += xv * Wt[k * 3 + 0];
        a1 += xv * Wt[k * 3 + 1];
        a2 += xv * Wt[k * 3 + 2];
    }
#pragma unroll
    for (int off = 16; off; off >>= 1) {
        a0 += __shfl_down_sync(0xffffffffu, a0, off);
        a1 += __shfl_down_sync(0xffffffffu, a1, off);
        a2 += __shfl_down_sync(0xffffffffu, a2, off);
    }
    if (lane == 0) {
        float r0 = fmaxf(a0 + agg3[warp * 3 + 0], 0.f);
        float r1 = fmaxf(a1 + agg3[warp * 3 + 1], 0.f);
        float r2 = fmaxf(a2 + agg3[warp * 3 + 2], 0.f);
        outpos[warp * 3 + 0] = vpos[warp * 3 + 0] + tanhf(r0);
        outpos[warp * 3 + 1] = vpos[warp * 3 + 1] + tanhf(r1);
        outpos[warp * 3 + 2] = vpos[warp * 3 + 2] + tanhf(r2);
    }
}

// ---------------- launch ----------------
extern "C" void kernel_launch(void* const* d_in, const int* in_sizes, int n_in,
                              void* d_out, int out_size)
{
    const float* f1   = (const float*)d_in[0];
    const float* f2   = (const float*)d_in[1];
    const float* f3   = (const float*)d_in[2];
    const float* f4   = (const float*)d_in[3];
    const float* vpos = (const float*)d_in[4];
    const float* vfea = (const float*)d_in[5];
    const int*   ei   = (const int*)d_in[6];
    const float* wlin = (const float*)d_in[7];
    const float* r0p  = (const float*)d_in[8];
    const float* r0a0 = (const float*)d_in[9];
    const float* r0a1 = (const float*)d_in[10];
    const float* r0b0 = (const float*)d_in[11];
    const float* r0b1 = (const float*)d_in[12];
    const float* r1a0 = (const float*)d_in[13];
    const float* r1a1 = (const float*)d_in[14];
    const float* r1b0 = (const float*)d_in[15];
    const float* r1b1 = (const float*)d_in[16];
    const float* r2a0 = (const float*)d_in[17];
    const float* r2a1 = (const float*)d_in[18];
    const float* r2b0 = (const float*)d_in[19];
    const float* r2b1 = (const float*)d_in[20];
    const float* gw0  = (const float*)d_in[21];
    const float* gw1  = (const float*)d_in[22];

    float* out  = (float*)d_out;
    float* hout = out + (long)VV * 3;

    float *P1, *P2, *P3, *P4, *feat, *hb, *tb, *Ab, *agg, *A3, *agg3;
    int *deg;
    cudaGetSymbolAddress((void**)&P1,   g_P1);
    cudaGetSymbolAddress((void**)&P2,   g_P2);
    cudaGetSymbolAddress((void**)&P3,   g_P3);
    cudaGetSymbolAddress((void**)&P4,   g_P4);
    cudaGetSymbolAddress((void**)&feat, g_feat);
    cudaGetSymbolAddress((void**)&hb,   g_h);
    cudaGetSymbolAddress((void**)&tb,   g_t);
    cudaGetSymbolAddress((void**)&Ab,   g_Ae);
    cudaGetSymbolAddress((void**)&agg,  g_agg);
    cudaGetSymbolAddress((void**)&A3,   g_A3);
    cudaGetSymbolAddress((void**)&agg3, g_agg3);
    cudaGetSymbolAddress((void**)&deg,  g_deg);

    // ---- CSR build (once per call; reused by all 7 aggregations) ----
    cudaMemsetAsync(deg, 0, VV * sizeof(int));
    k_hist<<<(EE + 255) / 256, 256>>>(ei);
    k_scan1<<<256, 128>>>();
    k_scan2<<<1, 256>>>();
    k_scan3<<<256, 128>>>();
    k_fill<<<(EE + 255) / 256, 256>>>(ei);

    // ---- per-pixel feature projections: P_m = fmap_m^T @ w_lin_slice ----
    // f1: 200 blocks, no split. f2/f3/f4: split-K with atomic accumulate.
    cudaMemsetAsync(P2, 0, (size_t)BB * 784 * 128 * sizeof(float));
    cudaMemsetAsync(P3, 0, (size_t)BB * 196 * 128 * sizeof(float));
    cudaMemsetAsync(P4, 0, (size_t)BB * 49 * 128 * sizeof(float));

    gemm128<0, true, false><<<dim3(25, 1, BB), 256>>>(
        f1, 3136, (long)256 * 3136, wlin + (long)0 * 128, nullptr, nullptr,
        P1, (long)3136 * 128, 3136, 256);
    gemm128<0, true, true><<<dim3(7, 4, BB), 256>>>(
        f2, 784, (long)512 * 784, wlin + (long)256 * 128, nullptr, nullptr,
        P2, (long)784 * 128, 784, 512);
    gemm128<0, true, true><<<dim3(2, 8, BB), 256>>>(
        f3, 196, (long)1024 * 196, wlin + (long)768 * 128, nullptr, nullptr,
        P3, (long)196 * 128, 196, 1024);
    gemm128<0, true, true><<<dim3(1, 16, BB), 256>>>(
        f4, 49, (long)2048 * 49, wlin + (long)1792 * 128, nullptr, nullptr,
        P4, (long)49 * 128, 49, 2048);

    // ---- assemble feat = [vertex_features | pos | vert_align @ w_lin] ----
    build_feat<<<VV / 4, 128>>>(vpos, vfea, feat);

    dim3 gV(VV / 128, 1, 1);
#define GEMM0(Ap, ldap, Wp, Kp, Cp) \
    gemm128<0, false, false><<<gV, 256>>>(Ap, ldap, 0, Wp, nullptr, nullptr, Cp, 0, VV, Kp)
#define GEMM1(Ap, ldap, Wp, Kp, Dp, Cp) \
    gemm128<1, false, false><<<gV, 256>>>(Ap, ldap, 0, Wp, Dp, nullptr, Cp, 0, VV, Kp)
#define GEMM2(Ap, ldap, Wp, Kp, Dp, Sp, Cp) \
    gemm128<2, false, false><<<gV, 256>>>(Ap, ldap, 0, Wp, Dp, Sp, Cp, 0, VV, Kp)
#define AGG(Ap) agg_gather<<<VV, 128>>>(Ap, agg)

    // ---- resg block 0 (input feat, K=259, projected skip) ----
    GEMM0(feat, LDF, r0p, IN0, hb);           // skip = feat @ r0p
    GEMM0(feat, LDF, r0a1, IN0, Ab);
    AGG(Ab);
    GEMM1(feat, LDF, r0a0, IN0, agg, tb);     // g1 = relu(feat@a0 + agg)
    GEMM0(tb, 128, r0b1, 128, Ab);
    AGG(Ab);
    GEMM2(tb, 128, r0b0, 128, agg, hb, hb);   // h0 = skip + relu(g1@b0 + agg)

    // ---- resg block 1 ----
    GEMM0(hb, 128, r1a1, 128, Ab);
    AGG(Ab);
    GEMM1(hb, 128, r1a0, 128, agg, tb);
    GEMM0(tb, 128, r1b1, 128, Ab);
    AGG(Ab);
    GEMM2(tb, 128, r1b0, 128, agg, hb, hb);

    // ---- resg block 2 (final h written straight into d_out) ----
    GEMM0(hb, 128, r2a1, 128, Ab);
    AGG(Ab);
    GEMM1(hb, 128, r2a0, 128, agg, tb);
    GEMM0(tb, 128, r2b1, 128, Ab);
    AGG(Ab);
    GEMM2(tb, 128, r2b0, 128, agg, hb, hout);

    // ---- position head: pos + tanh(gconv(h, gw0, gw1)) ----
    gemv3<<<VV / 8, 256>>>(hout, gw1, A3);
    k_agg3<<<VV / 256, 256>>>(A3, agg3);
    final_pos<<<VV / 8, 256>>>(hout, gw0, agg3, vpos, out);

#undef GEMM0
#undef GEMM1
#undef GEMM2
#undef AGG
}